// round 9
// baseline (speedup 1.0000x reference)
#include <cuda_runtime.h>
#include <cstdint>

#define FULLMASK 0xffffffffu
typedef unsigned long long ull;

static constexpr int Hh     = 5;
static constexpr int Tt     = 512;
static constexpr int Bb     = 8192;
static constexpr int CHUNK  = 4;            // timesteps per chunk (z in regs)
static constexpr int NCHUNK = Tt / CHUNK;   // 128
static constexpr int EPW    = 3;            // elements per warp (10 lanes each)
static constexpr int BLOCK  = 32;
static constexpr int GRID   = (Bb + EPW - 1) / EPW;   // 2731
static constexpr int ROWF   = Tt * Hh;      // 2560
static constexpr int CH_FL  = CHUNK * Hh;   // 20 floats per element per chunk

// ---------- packed f32x2 helpers ----------
__device__ __forceinline__ ull pack2(float lo, float hi) {
    ull r; asm("mov.b64 %0, {%1, %2};" : "=l"(r) : "f"(lo), "f"(hi)); return r;
}
__device__ __forceinline__ void unpack2(ull v, float& lo, float& hi) {
    asm("mov.b64 {%0, %1}, %2;" : "=f"(lo), "=f"(hi) : "l"(v));
}
__device__ __forceinline__ ull fma2(ull a, ull b, ull c) {
    ull d; asm("fma.rn.f32x2 %0, %1, %2, %3;" : "=l"(d) : "l"(a), "l"(b), "l"(c));
    return d;
}
__device__ __forceinline__ float tanh_fast(float x) {
    float y; asm("tanh.approx.f32 %0, %1;" : "=f"(y) : "f"(x)); return y;
}

// ============================================================================
// Fused LSTM + head. One warp/CTA, 3 elements, 10 lanes/element.
// Lane (e, half, sub): half0 owns gate-row pair (i_sub, g_sub) packed f32x2,
//                      half1 owns (f_sub, o_sub) + state cst[sub], hs[sub]=2h.
// Sigmoid folding: acc for i/f/o = z/2; hs = 2h.
//   W_ih: i/f/o *0.5, g *1 ; W_hh: i/f/o *0.25, g *0.5 (folded at load).
// Serial loop: z (x-projection) precomputed into registers per 4-step chunk;
// h exchanged via smem duplicated pairs (1 STS.64 publish, 2 LDS.128 + 1
// LDS.64 fetch), p via single SHFL.
// ============================================================================
__global__ void __launch_bounds__(BLOCK, 19)
fused_kernel(const float* __restrict__ x,
             const float* __restrict__ W_ih, const float* __restrict__ W_hh,
             const float* __restrict__ b_ih, const float* __restrict__ b_hh,
             const float* __restrict__ W1, const float* __restrict__ b1,
             const float* __restrict__ W2, const float* __restrict__ b2,
             const float* __restrict__ W3, const float* __restrict__ b3,
             float* __restrict__ out)
{
    // dup-x staging: [buf][e][k][t] as (v,v) ull; precompute reads LDS.128
    __shared__ __align__(16) ull   sxx[2][EPW][Hh][CHUNK];   // 960 B
    __shared__ __align__(16) float hsm[EPW][12];             // dup h pairs, 48B/elem
    __shared__ float sW1[32 * 5], sb1[32], sb2[32], sb3[5];
    __shared__ float sW2[32 * 33];
    __shared__ float sW3[5 * 33];
    __shared__ float hres[EPW * Hh];

    const int lane = threadIdx.x;
    const int r10  = (lane < 30) ? lane : 29;   // lanes 30/31 mirror lane 29
    const int e    = r10 / 10;
    const int rr   = r10 - e * 10;
    const int half = rr / 5;                    // 0:(i,g)  1:(f,o)+state
    const int sub  = rr - half * 5;

    const int base = blockIdx.x * EPW;
    const int gb   = base + e;

    // ---- per-lane packed weights (scale folding as round 8) ----
    const int r0 = sub + half * 5;              // i_sub | f_sub
    const int r1 = sub + 10 + half * 5;         // g_sub | o_sub
    const float sxlo = 0.5f;
    const float sxhi = half ? 0.5f  : 1.0f;
    const float shlo = 0.25f;
    const float shhi = half ? 0.25f : 0.5f;

    ull wx[5], wh[5];
#pragma unroll
    for (int k = 0; k < 5; ++k) {
        wx[k] = pack2(sxlo * W_ih[r0 * 5 + k], sxhi * W_ih[r1 * 5 + k]);
        wh[k] = pack2(shlo * W_hh[r0 * 5 + k], shhi * W_hh[r1 * 5 + k]);
    }
    const ull bias = pack2(sxlo * (b_ih[r0] + b_hh[r0]),
                           sxhi * (b_ih[r1] + b_hh[r1]));

    const int psrc = e * 10 + sub;              // p source (half0 lane, same sub)

    // ---- head weights to smem (one-time) ----
    for (int i = lane; i < 160; i += BLOCK) sW1[i] = W1[i];
    for (int i = lane; i < 1024; i += BLOCK) sW2[(i >> 5) * 33 + (i & 31)] = W2[i];
    for (int i = lane; i < 160; i += BLOCK) sW3[(i >> 5) * 33 + (i & 31)] = W3[i];
    if (lane < 32) { sb1[lane] = b1[lane]; sb2[lane] = b2[lane]; }
    if (lane < 5)  sb3[lane] = b3[lane];

    // zero h (h0 = 0)
    for (int i = lane; i < EPW * 12; i += BLOCK) ((float*)hsm)[i] = 0.0f;

    const float4 z4c = make_float4(0.f, 0.f, 0.f, 0.f);
    // staging geometry: lanes 0..14 each carry one float4 (20 floats/elem/chunk)
    const int se = lane / 5;                    // staged element (valid lane<15)
    const int sq = (lane % 5) * 4;              // float offset within elem chunk

#define STAGE_LDG(C)                                                          \
    do { pf = z4c;                                                            \
        if (lane < 15) { const int gb0 = base + se;                           \
            if (gb0 < Bb)                                                     \
                pf = *(const float4*)(x + gb0 * ROWF + (C) * CH_FL + sq); }   \
    } while (0)

#define STAGE_STS(BUF)                                                        \
    do { if (lane < 15) { const float* ap = &pf.x;                            \
        _Pragma("unroll")                                                     \
        for (int j = 0; j < 4; ++j) {                                         \
            const int fl = sq + j, t = fl / 5, k = fl - 5 * t;                \
            sxx[BUF][se][k][t] = pack2(ap[j], ap[j]); } }                     \
    } while (0)

#define PRECOMP(Z, BUF)                                                       \
    do { Z[0] = bias; Z[1] = bias; Z[2] = bias; Z[3] = bias;                  \
        _Pragma("unroll")                                                     \
        for (int k = 0; k < 5; ++k) {                                         \
            const ulonglong2 a = *(const ulonglong2*)(&sxx[BUF][e][k][0]);    \
            const ulonglong2 b = *(const ulonglong2*)(&sxx[BUF][e][k][2]);    \
            Z[0] = fma2(wx[k], a.x, Z[0]);  Z[1] = fma2(wx[k], a.y, Z[1]);    \
            Z[2] = fma2(wx[k], b.x, Z[2]);  Z[3] = fma2(wx[k], b.y, Z[3]); }  \
    } while (0)

#define STEP(Z, TL)                                                           \
    do { __syncwarp();                                                        \
        const ulonglong2 h01 = *(const ulonglong2*)(&hsm[e][0]);              \
        const ulonglong2 h23 = *(const ulonglong2*)(&hsm[e][4]);              \
        const ull h4 = *(const ull*)(&hsm[e][8]);                             \
        ull acc = Z[TL];                                                      \
        acc = fma2(wh[0], h01.x, acc);                                        \
        acc = fma2(wh[1], h01.y, acc);                                        \
        acc = fma2(wh[2], h23.x, acc);                                        \
        acc = fma2(wh[3], h23.y, acc);                                        \
        acc = fma2(wh[4], h4,    acc);                                        \
        float z0, z1; unpack2(acc, z0, z1);                                   \
        const float T0 = tanh_fast(z0), T1 = tanh_fast(z1);                   \
        const float p  = fmaf(T0, T1, T1);        /* half0: 2ig */            \
        const float pp = __shfl_sync(FULLMASK, p, psrc);                      \
        const float u  = fmaf(T0, cst, cst);      /* half1: 2fc */            \
        cst = fmaf(0.5f, u, 0.5f * pp);                                       \
        const float Tc = tanh_fast(cst);                                      \
        hs = fmaf(T1, Tc, Tc);                    /* half1: new 2h */         \
        if (half) *(ull*)(&hsm[e][2 * sub]) = pack2(hs, hs);                  \
    } while (0)

#define BODY(C, ZU, ZF, BUFR, BUFW)                                           \
    do { __syncwarp();                                                        \
        float4 pf;                                                            \
        const bool dost = ((C) + 2 < NCHUNK);                                 \
        if (dost) STAGE_LDG((C) + 2); else pf = z4c;                          \
        if ((C) + 1 < NCHUNK) PRECOMP(ZF, BUFR);                              \
        STEP(ZU, 0); STEP(ZU, 1); STEP(ZU, 2); STEP(ZU, 3);                   \
        if (dost) STAGE_STS(BUFW);                                            \
    } while (0)

    // ---- prologue: stage chunks 0,1; precompute z(chunk0) ----
    {
        float4 pf;
        STAGE_LDG(0); STAGE_STS(0);
        STAGE_LDG(1); STAGE_STS(1);
    }
    __syncwarp();

    ull zA[4], zB[4];
    float cst = 0.0f, hs = 0.0f;
    PRECOMP(zA, 0);

    for (int cc = 0; cc < NCHUNK; cc += 2) {
        BODY(cc,     zA, zB, 1, 0);   // serial on zA; fill zB=z(cc+1); stage cc+2 -> buf0
        BODY(cc + 1, zB, zA, 0, 1);   // serial on zB; fill zA=z(cc+2); stage cc+3 -> buf1
    }

    // ==================== fused head ====================
    if (lane < 30 && half == 1 && gb < Bb)
        hres[e * Hh + sub] = 0.5f * hs + x[gb * ROWF + (Tt - 1) * Hh + sub];
    __syncwarp();

#pragma unroll
    for (int ee = 0; ee < EPW; ++ee) {
        const int g = base + ee;
        float a1 = sb1[lane];
#pragma unroll
        for (int k = 0; k < 5; ++k)
            a1 = fmaf(sW1[lane * 5 + k], hres[ee * Hh + k], a1);   // LDS bcast
        a1 = fmaxf(a1, 0.0f);

        float a2 = sb2[lane];
#pragma unroll
        for (int k = 0; k < 32; ++k)
            a2 = fmaf(sW2[lane * 33 + k], __shfl_sync(FULLMASK, a1, k), a2);
        a2 = fmaxf(a2, 0.0f);

        const int wrow = (lane < 5) ? lane : 0;
        float o = (lane < 5) ? sb3[lane] : 0.0f;
#pragma unroll
        for (int k = 0; k < 32; ++k)
            o = fmaf(sW3[wrow * 33 + k], __shfl_sync(FULLMASK, a2, k), o);

        if (lane < 5 && g < Bb) out[g * Hh + lane] = o;
    }

#undef STAGE_LDG
#undef STAGE_STS
#undef PRECOMP
#undef STEP
#undef BODY
}

// ============================================================================
extern "C" void kernel_launch(void* const* d_in, const int* in_sizes, int n_in,
                              void* d_out, int out_size) {
    const float* x    = (const float*)d_in[0];
    const float* W_ih = (const float*)d_in[1];
    const float* W_hh = (const float*)d_in[2];
    const float* b_ih = (const float*)d_in[3];
    const float* b_hh = (const float*)d_in[4];
    const float* W1   = (const float*)d_in[5];
    const float* b1   = (const float*)d_in[6];
    const float* W2   = (const float*)d_in[7];
    const float* b2   = (const float*)d_in[8];
    const float* W3   = (const float*)d_in[9];
    const float* b3   = (const float*)d_in[10];
    float* out = (float*)d_out;

    fused_kernel<<<GRID, BLOCK>>>(x, W_ih, W_hh, b_ih, b_hh,
                                  W1, b1, W2, b2, W3, b3, out);
    (void)in_sizes; (void)n_in; (void)out_size;
}

// round 10
// speedup vs baseline: 1.0069x; 1.0069x over previous
#include <cuda_runtime.h>
#include <cstdint>

#define FULLMASK 0xffffffffu
typedef unsigned long long ull;

static constexpr int Hh     = 5;
static constexpr int Tt     = 512;
static constexpr int Bb     = 8192;
static constexpr int CHUNK  = 8;            // timesteps per smem chunk
static constexpr int NCHUNK = Tt / CHUNK;   // 64
static constexpr int EPW    = 6;            // elements per warp (5 lanes each)
static constexpr int BLOCK  = 32;
static constexpr int GRID   = (Bb + EPW - 1) / EPW;   // 1366
static constexpr int ROWF   = Tt * Hh;      // 2560
static constexpr int CH_FL  = CHUNK * Hh;   // 40 floats per element per chunk

// ---------- packed f32x2 helpers ----------
__device__ __forceinline__ ull pack2(float lo, float hi) {
    ull r; asm("mov.b64 %0, {%1, %2};" : "=l"(r) : "f"(lo), "f"(hi)); return r;
}
__device__ __forceinline__ void unpack2(ull v, float& lo, float& hi) {
    asm("mov.b64 {%0, %1}, %2;" : "=f"(lo), "=f"(hi) : "l"(v));
}
__device__ __forceinline__ ull fma2(ull a, ull b, ull c) {
    ull d; asm("fma.rn.f32x2 %0, %1, %2, %3;" : "=l"(d) : "l"(a), "l"(b), "l"(c));
    return d;
}
__device__ __forceinline__ float tanh_fast(float x) {
    float y; asm("tanh.approx.f32 %0, %1;" : "=f"(y) : "f"(x)); return y;
}

// ============================================================================
// Fused LSTM + head. One warp/CTA, 6 elements, 5 lanes/element.
// Lane (e, sub) owns ALL FOUR gate rows at component `sub`:
//   packed accs: aIF = (i_sub, f_sub),  aGO = (g_sub, o_sub),
// plus the full state c[sub], hs[sub] = 2*h[sub]  (no cross-lane epilogue).
// Only cross-lane traffic: 5-wide h broadcast per step (5 SHFL).
// Sigmoid folding: acc for i/f/o rows = z/2; internal state hs = 2h.
//   W_ih: i/f/o *0.5, g *1 ; W_hh: i/f/o *0.25, g *0.5 (folded at load).
//   i=0.5*tanh(zi/2)+0.5 etc => 2ig=fma(Ti,Tg,Tg); 2fc=fma(Tf,c,c);
//   c' = 0.5*(2fc+2ig);  hs' = fma(To,Tc,Tc).
// ============================================================================
__global__ void __launch_bounds__(BLOCK)
fused_kernel(const float* __restrict__ x,
             const float* __restrict__ W_ih, const float* __restrict__ W_hh,
             const float* __restrict__ b_ih, const float* __restrict__ b_hh,
             const float* __restrict__ W1, const float* __restrict__ b1,
             const float* __restrict__ W2, const float* __restrict__ b2,
             const float* __restrict__ W3, const float* __restrict__ b3,
             float* __restrict__ out)
{
    __shared__ ull   sx[2][CHUNK][EPW][Hh];   // x duplicated (v,v): 3840 B
    __shared__ float sW1[32 * 5], sb1[32], sb2[32], sb3[5];
    __shared__ float sW2[32 * 33];            // padded rows
    __shared__ float sW3[5 * 33];
    __shared__ float hres[EPW * Hh];

    const int lane = threadIdx.x;
    const int r30  = (lane < 30) ? lane : 29;  // lanes 30/31 mirror lane 29
    const int e    = r30 / 5;
    const int sub  = r30 - e * 5;

    const int base = blockIdx.x * EPW;
    const int gb   = base + e;
    const bool ev  = (gb < Bb);

    // ---- per-lane packed weights: rows (i_sub,f_sub) and (g_sub,o_sub) ----
    ull wxIF[5], wxGO[5], whIF[5], whGO[5];
#pragma unroll
    for (int k = 0; k < 5; ++k) {
        wxIF[k] = pack2(0.50f * W_ih[(sub     ) * 5 + k],
                        0.50f * W_ih[(sub + 5 ) * 5 + k]);
        wxGO[k] = pack2(        W_ih[(sub + 10) * 5 + k],
                        0.50f * W_ih[(sub + 15) * 5 + k]);
        whIF[k] = pack2(0.25f * W_hh[(sub     ) * 5 + k],
                        0.25f * W_hh[(sub + 5 ) * 5 + k]);
        whGO[k] = pack2(0.50f * W_hh[(sub + 10) * 5 + k],
                        0.25f * W_hh[(sub + 15) * 5 + k]);
    }
    const ull bIF = pack2(0.5f * (b_ih[sub     ] + b_hh[sub     ]),
                          0.5f * (b_ih[sub + 5 ] + b_hh[sub + 5 ]));
    const ull bGO = pack2(       (b_ih[sub + 10] + b_hh[sub + 10]),
                          0.5f * (b_ih[sub + 15] + b_hh[sub + 15]));

    const int hbase = e * 5;                  // shfl source base for h broadcast

    // ---- head weights to smem (one-time) ----
    for (int i = lane; i < 160; i += BLOCK) sW1[i] = W1[i];
    for (int i = lane; i < 1024; i += BLOCK) sW2[(i >> 5) * 33 + (i & 31)] = W2[i];
    for (int i = lane; i < 160; i += BLOCK) sW3[(i >> 5) * 33 + (i & 31)] = W3[i];
    if (lane < 32) { sb1[lane] = b1[lane]; sb2[lane] = b2[lane]; }
    if (lane < 5)  sb3[lane] = b3[lane];

    // ---- staging geometry: lane covers floats [lo, lo+8) of its element ----
    // per chunk: elem chunk = 40 floats; (lane%5)*8 gives two float4 loads.
    const int lo = sub * 8;                   // 0,8,16,24,32 (float4-aligned)
    const float4 z4c = make_float4(0.f, 0.f, 0.f, 0.f);

#define STAGE_LDG(C)                                                          \
    do { pfa = z4c; pfb = z4c;                                                \
        if (lane < 30 && ev) {                                                \
            const float* src = x + gb * ROWF + (C) * CH_FL + lo;              \
            pfa = *(const float4*)(src);                                      \
            pfb = *(const float4*)(src + 4);                                  \
        }                                                                     \
    } while (0)

#define STAGE_STS(BUF)                                                        \
    do { if (lane < 30) {                                                     \
        const float* ap = &pfa.x; const float* bp = &pfb.x;                   \
        _Pragma("unroll")                                                     \
        for (int j = 0; j < 8; ++j) {                                         \
            const float v = (j < 4) ? ap[j] : bp[j - 4];                      \
            const int f = lo + j, t = f / 5, k = f - 5 * t;                   \
            sx[BUF][t][e][k] = pack2(v, v); } }                               \
    } while (0)

    // ---- prologue: stage chunk 0 ----
    float4 pfa, pfb;
    STAGE_LDG(0);
    STAGE_STS(0);
    __syncwarp();

    float cst = 0.0f;      // true c[sub]
    float hs  = 0.0f;      // 2*h[sub]

    for (int ch = 0; ch < NCHUNK; ++ch) {
        // prefetch next chunk into registers (LDG latency hidden by 8 steps)
        if (ch + 1 < NCHUNK) STAGE_LDG(ch + 1);

        const int buf = ch & 1;
#pragma unroll
        for (int tl = 0; tl < CHUNK; ++tl) {
            const ull* xr = &sx[buf][tl][e][0];
            ull aIF = bIF, aGO = bGO;
#pragma unroll
            for (int k = 0; k < 5; ++k) {
                const float hk = __shfl_sync(FULLMASK, hs, hbase + k);
                const ull hd = pack2(hk, hk);
                aIF = fma2(whIF[k], hd, aIF);
                aGO = fma2(whGO[k], hd, aGO);
            }
#pragma unroll
            for (int k = 0; k < 5; ++k) {
                const ull xk = xr[k];               // (x_k, x_k) LDS.64
                aIF = fma2(wxIF[k], xk, aIF);
                aGO = fma2(wxGO[k], xk, aGO);
            }
            float zi, zf, zg, zo;
            unpack2(aIF, zi, zf);
            unpack2(aGO, zg, zo);
            const float Ti = tanh_fast(zi);
            const float Tf = tanh_fast(zf);
            const float Tg = tanh_fast(zg);
            const float To = tanh_fast(zo);
            const float u = fmaf(Tf, cst, cst);     // 2*f*c
            const float v = fmaf(Ti, Tg, Tg);       // 2*i*g
            cst = fmaf(0.5f, u, 0.5f * v);          // new c
            const float Tc = tanh_fast(cst);
            hs = fmaf(To, Tc, Tc);                  // new 2*h
        }

        if (ch + 1 < NCHUNK) STAGE_STS((ch + 1) & 1);
        __syncwarp();
    }

    // ==================== fused head ====================
    if (lane < 30 && ev)
        hres[e * Hh + sub] = 0.5f * hs + x[gb * ROWF + (Tt - 1) * Hh + sub];
    __syncwarp();

#pragma unroll
    for (int ee = 0; ee < EPW; ++ee) {
        const int g = base + ee;
        float a1 = sb1[lane];
#pragma unroll
        for (int k = 0; k < 5; ++k)
            a1 = fmaf(sW1[lane * 5 + k], hres[ee * Hh + k], a1);   // LDS bcast
        a1 = fmaxf(a1, 0.0f);

        float a2 = sb2[lane];
#pragma unroll
        for (int k = 0; k < 32; ++k)
            a2 = fmaf(sW2[lane * 33 + k], __shfl_sync(FULLMASK, a1, k), a2);
        a2 = fmaxf(a2, 0.0f);

        const int wrow = (lane < 5) ? lane : 0;
        float o = (lane < 5) ? sb3[lane] : 0.0f;
#pragma unroll
        for (int k = 0; k < 32; ++k)
            o = fmaf(sW3[wrow * 33 + k], __shfl_sync(FULLMASK, a2, k), o);

        if (lane < 5 && g < Bb) out[g * Hh + lane] = o;
    }

#undef STAGE_LDG
#undef STAGE_STS
}

// ============================================================================
extern "C" void kernel_launch(void* const* d_in, const int* in_sizes, int n_in,
                              void* d_out, int out_size) {
    const float* x    = (const float*)d_in[0];
    const float* W_ih = (const float*)d_in[1];
    const float* W_hh = (const float*)d_in[2];
    const float* b_ih = (const float*)d_in[3];
    const float* b_hh = (const float*)d_in[4];
    const float* W1   = (const float*)d_in[5];
    const float* b1   = (const float*)d_in[6];
    const float* W2   = (const float*)d_in[7];
    const float* b2   = (const float*)d_in[8];
    const float* W3   = (const float*)d_in[9];
    const float* b3   = (const float*)d_in[10];
    float* out = (float*)d_out;

    fused_kernel<<<GRID, BLOCK>>>(x, W_ih, W_hh, b_ih, b_hh,
                                  W1, b1, W2, b2, W3, b3, out);
    (void)in_sizes; (void)n_in; (void)out_size;
}

// round 12
// speedup vs baseline: 1.1305x; 1.1227x over previous
#include <cuda_runtime.h>
#include <cstdint>

#define FULLMASK 0xffffffffu
typedef unsigned long long ull;

static constexpr int Hh     = 5;
static constexpr int Tt     = 512;
static constexpr int Bb     = 8192;
static constexpr int CHUNK  = 8;            // timesteps per smem chunk
static constexpr int NCHUNK = Tt / CHUNK;   // 64
static constexpr int EPW    = 16;           // elements per warp (2 lanes each)
static constexpr int BLOCK  = 32;
static constexpr int GRID   = Bb / EPW;     // 512  (exact: no bounds checks!)
static constexpr int ROWF   = Tt * Hh;      // 2560
static constexpr int CH_FL  = CHUNK * Hh;   // 40 floats per element per chunk

// ---------- packed f32x2 helpers ----------
__device__ __forceinline__ ull pack2(float lo, float hi) {
    ull r; asm("mov.b64 %0, {%1, %2};" : "=l"(r) : "f"(lo), "f"(hi)); return r;
}
__device__ __forceinline__ void unpack2(ull v, float& lo, float& hi) {
    asm("mov.b64 {%0, %1}, %2;" : "=f"(lo), "=f"(hi) : "l"(v));
}
__device__ __forceinline__ ull fma2(ull a, ull b, ull c) {
    ull d; asm("fma.rn.f32x2 %0, %1, %2, %3;" : "=l"(d) : "l"(a), "l"(b), "l"(c));
    return d;
}
__device__ __forceinline__ float tanh_fast(float x) {
    float y; asm("tanh.approx.f32 %0, %1;" : "=f"(y) : "f"(x)); return y;
}

// ============================================================================
// Fused LSTM + head. One warp/CTA, 16 elements, 2 lanes/element (ALL 32 busy).
// lane = 2*e + role.  role0 owns pair-rows (i_s, g_s) for s=0..4,
//                     role1 owns (f_s, o_s) + state c_s, hs_s = 2*h_s.
// Sigmoid folding (proven, rel_err 7.2e-7): accs for i/f/o rows hold z/2,
// g rows hold z; internal state hs = 2h.  Folded scales:
//   W_ih: i/f/o *0.5, g *1 ;  W_hh: i/f/o *0.25, g *0.5 ; biases likewise.
// Uniform per-component epilogue (both roles execute identical instructions):
//   T0 = tanh(acc.lo)  [Ti | Tf],  T1 = tanh(acc.hi)  [Tg | To]
//   a  = fma(T0,T1,T1)           -> role0: p = 2ig   (role1: ignored)
//   pp = shfl(a, lane&~1)        -> p from role0
//   u  = fma(T0,c,c)             -> role1: 2fc
//   c  = 0.5*u + 0.5*pp          -> role1: new c     (role0: bounded garbage)
//   Tc = tanh(c); hs = fma(T1,Tc,Tc) -> role1: new 2h
// Cross-lane per step: 5 h-shfl (from lane|1) + 5 p-shfl (from lane&~1).
// ============================================================================
__global__ void __launch_bounds__(BLOCK)
fused_kernel(const float* __restrict__ x,
             const float* __restrict__ W_ih, const float* __restrict__ W_hh,
             const float* __restrict__ b_ih, const float* __restrict__ b_hh,
             const float* __restrict__ W1, const float* __restrict__ b1,
             const float* __restrict__ W2, const float* __restrict__ b2,
             const float* __restrict__ W3, const float* __restrict__ b3,
             float* __restrict__ out)
{
    __shared__ ull   sx[2][CHUNK][EPW][Hh];   // x dup pairs: 10240 B
    __shared__ float sW1[32 * 5], sb1[32], sb2[32], sb3[5];
    __shared__ float sW2[32 * 33];            // padded rows
    __shared__ float sW3[5 * 33];
    __shared__ float hres[EPW * Hh];

    const int lane = threadIdx.x;
    const int e    = lane >> 1;
    const int role = lane & 1;

    const int base = blockIdx.x * EPW;
    const int gb   = base + e;

    // ---- per-lane packed weights: 5 pair-rows x (5 x-cols + 5 h-cols) ----
    // role0: rows (s, s+10) = (i_s, g_s); role1: rows (s+5, s+15) = (f_s, o_s)
    const int rlo = 5 * role;                 // +0 | +5
    const int rhi = 10 + 5 * role;            // +10 | +15
    const float xhi = role ? 0.5f : 1.0f;     // g unscaled, o *0.5
    const float hhi = role ? 0.25f : 0.5f;

    ull wx[5][5], wh[5][5], bias[5];
#pragma unroll
    for (int s = 0; s < 5; ++s) {
#pragma unroll
        for (int k = 0; k < 5; ++k) {
            wx[s][k] = pack2(0.50f * W_ih[(s + rlo) * 5 + k],
                             xhi   * W_ih[(s + rhi) * 5 + k]);
            wh[s][k] = pack2(0.25f * W_hh[(s + rlo) * 5 + k],
                             hhi   * W_hh[(s + rhi) * 5 + k]);
        }
        bias[s] = pack2(0.5f * (b_ih[s + rlo] + b_hh[s + rlo]),
                        xhi  * (b_ih[s + rhi] + b_hh[s + rhi]));
    }

    // ---- head weights to smem (one-time) ----
    for (int i = lane; i < 160; i += BLOCK) sW1[i] = W1[i];
    for (int i = lane; i < 1024; i += BLOCK) sW2[(i >> 5) * 33 + (i & 31)] = W2[i];
    for (int i = lane; i < 160; i += BLOCK) sW3[(i >> 5) * 33 + (i & 31)] = W3[i];
    if (lane < 32) { sb1[lane] = b1[lane]; sb2[lane] = b2[lane]; }
    if (lane < 5)  sb3[lane] = b3[lane];

    // ---- staging: lane covers floats [role*20, role*20+20) of its element ----
    const int lo = role * 20;                 // 16B-aligned (80 B)

#define STAGE_LDG(C)                                                          \
    do { const float* src = x + gb * ROWF + (C) * CH_FL + lo;                 \
        pf0 = *(const float4*)(src);                                          \
        pf1 = *(const float4*)(src + 4);                                      \
        pf2 = *(const float4*)(src + 8);                                      \
        pf3 = *(const float4*)(src + 12);                                     \
        pf4 = *(const float4*)(src + 16);                                     \
    } while (0)

#define STAGE_STS(BUF)                                                        \
    do { const float* ap[5] = {&pf0.x, &pf1.x, &pf2.x, &pf3.x, &pf4.x};       \
        _Pragma("unroll")                                                     \
        for (int j = 0; j < 20; ++j) {                                        \
            const float v = ap[j >> 2][j & 3];                                \
            const int f = lo + j, t = f / 5, k = f - 5 * t;                   \
            sx[BUF][t][e][k] = pack2(v, v); }                                 \
    } while (0)

    float4 pf0, pf1, pf2, pf3, pf4;
    STAGE_LDG(0);
    STAGE_STS(0);
    __syncwarp();

    float c[5]  = {0.f, 0.f, 0.f, 0.f, 0.f};
    float hs[5] = {0.f, 0.f, 0.f, 0.f, 0.f};  // role1: 2*h_s

    for (int ch = 0; ch < NCHUNK; ++ch) {
        if (ch + 1 < NCHUNK) STAGE_LDG(ch + 1);

        const int buf = ch & 1;
#pragma unroll
        for (int tl = 0; tl < CHUNK; ++tl) {
            const ull* xr = &sx[buf][tl][e][0];
            ull a0 = bias[0], a1 = bias[1], a2 = bias[2], a3 = bias[3], a4 = bias[4];

            // x-projection (off the serial chain; xr independent of h)
#pragma unroll
            for (int k = 0; k < 5; ++k) {
                const ull xk = xr[k];                    // dup pair, LDS.64 bcast
                a0 = fma2(wx[0][k], xk, a0);
                a1 = fma2(wx[1][k], xk, a1);
                a2 = fma2(wx[2][k], xk, a2);
                a3 = fma2(wx[3][k], xk, a3);
                a4 = fma2(wx[4][k], xk, a4);
            }
            // h-projection (on the chain; h from partner role1 lane)
#pragma unroll
            for (int k = 0; k < 5; ++k) {
                const float hk = __shfl_sync(FULLMASK, hs[k], lane | 1);
                const ull hd = pack2(hk, hk);
                a0 = fma2(wh[0][k], hd, a0);
                a1 = fma2(wh[1][k], hd, a1);
                a2 = fma2(wh[2][k], hd, a2);
                a3 = fma2(wh[3][k], hd, a3);
                a4 = fma2(wh[4][k], hd, a4);
            }

            // uniform epilogue, 5 independent component chains
            const ull av[5] = {a0, a1, a2, a3, a4};
#pragma unroll
            for (int s = 0; s < 5; ++s) {
                float z0, z1; unpack2(av[s], z0, z1);
                const float T0 = tanh_fast(z0);          // Ti | Tf
                const float T1 = tanh_fast(z1);          // Tg | To
                const float pa = fmaf(T0, T1, T1);       // role0: 2ig
                const float pp = __shfl_sync(FULLMASK, pa, lane & ~1);
                const float u  = fmaf(T0, c[s], c[s]);   // role1: 2fc
                c[s] = fmaf(0.5f, u, 0.5f * pp);         // role1: new c
                const float Tc = tanh_fast(c[s]);
                hs[s] = fmaf(T1, Tc, Tc);                // role1: new 2h
            }
        }

        if (ch + 1 < NCHUNK) STAGE_STS((ch + 1) & 1);
        __syncwarp();
    }

    // ==================== fused head ====================
    if (role == 1) {
#pragma unroll
        for (int s = 0; s < 5; ++s)
            hres[e * Hh + s] = 0.5f * hs[s] + x[gb * ROWF + (Tt - 1) * Hh + s];
    }
    __syncwarp();

#pragma unroll 4
    for (int ee = 0; ee < EPW; ++ee) {
        const int g = base + ee;
        float a1 = sb1[lane];
#pragma unroll
        for (int k = 0; k < 5; ++k)
            a1 = fmaf(sW1[lane * 5 + k], hres[ee * Hh + k], a1);   // LDS bcast
        a1 = fmaxf(a1, 0.0f);

        float a2 = sb2[lane];
#pragma unroll
        for (int k = 0; k < 32; ++k)
            a2 = fmaf(sW2[lane * 33 + k], __shfl_sync(FULLMASK, a1, k), a2);
        a2 = fmaxf(a2, 0.0f);

        const int wrow = (lane < 5) ? lane : 0;
        float o = (lane < 5) ? sb3[lane] : 0.0f;
#pragma unroll
        for (int k = 0; k < 32; ++k)
            o = fmaf(sW3[wrow * 33 + k], __shfl_sync(FULLMASK, a2, k), o);

        if (lane < 5) out[g * Hh + lane] = o;
    }

#undef STAGE_LDG
#undef STAGE_STS
}

// ============================================================================
extern "C" void kernel_launch(void* const* d_in, const int* in_sizes, int n_in,
                              void* d_out, int out_size) {
    const float* x    = (const float*)d_in[0];
    const float* W_ih = (const float*)d_in[1];
    const float* W_hh = (const float*)d_in[2];
    const float* b_ih = (const float*)d_in[3];
    const float* b_hh = (const float*)d_in[4];
    const float* W1   = (const float*)d_in[5];
    const float* b1   = (const float*)d_in[6];
    const float* W2   = (const float*)d_in[7];
    const float* b2   = (const float*)d_in[8];
    const float* W3   = (const float*)d_in[9];
    const float* b3   = (const float*)d_in[10];
    float* out = (float*)d_out;

    fused_kernel<<<GRID, BLOCK>>>(x, W_ih, W_hh, b_ih, b_hh,
                                  W1, b1, W2, b2, W3, b3, out);
    (void)in_sizes; (void)n_in; (void)out_size;
}